// round 15
// baseline (speedup 1.0000x reference)
#include <cuda_runtime.h>

// DistPtsTopo via per-cell moments + separable tri factorization.
//   D_t = alpha_a + beta_b + 2n (G_a . F_b),  G_a = F_0 + F_a
// k_bin: 1 point/thread moment REDs (no return) + 1 node/thread repack of
// offset into node-major float4 (g_off4) -> k_main gathers 8x LDG.128.
// k_main: one thread per cell, 5-instr inner loop, direct scalar STS,
// 128-bit smem transpose drain. launch_bounds(128,8) -> 64 regs, 50% occ cap.
// inputs: d_in[0] = offset (3,65,65,65) f32, d_in[1] = points (300000,3) f32
// output: (64^3, 48) f32.

#define NN      65
#define NN2     (NN*NN)
#define NN3     (NN*NN*NN)
#define PTS     300000
#define NCELL   (64*64*64)       // 262144
#define MTPB    128
#define PITCH   52               // 48 + 4 pad words: conflict-free 128-bit smem ops
#define BINTPB  256
#define BINBLK  ((PTS + BINTPB - 1) / BINTPB)   // 1172 blocks, 300032 threads

// scratch: zero at module load; k_main self-resets moments after reading.
__device__ float4 g_momA[NCELL];   // (SumRx, SumRy, SumRz, Sum|r|^2)
__device__ float  g_momN[NCELL];   // point count
__device__ float4 g_off4[NN3];     // node-major repacked offset (x,y,z,0)

// ---------------- kernel 1: moments (1 pt/thread) + offset repack (1 node/thread) --
__global__ __launch_bounds__(BINTPB) void k_bin(const float* __restrict__ points,
                                                const float* __restrict__ offset) {
    int t = blockIdx.x * blockDim.x + threadIdx.x;

    // independent work: repack one node into node-major float4
    if (t < NN3) {
        g_off4[t] = make_float4(__ldg(offset + t),
                                __ldg(offset + NN3 + t),
                                __ldg(offset + 2 * NN3 + t), 0.f);
    }

    if (t >= PTS) return;

    float px = __ldg(points + 3 * t + 0);
    float py = __ldg(points + 3 * t + 1);
    float pz = __ldg(points + 3 * t + 2);

    int ci = min(max(__float2int_rd(px), 0), NN - 2);
    int cj = min(max(__float2int_rd(py), 0), NN - 2);
    int ck = min(max(__float2int_rd(pz), 0), NN - 2);
    int c = (ci * 64 + cj) * 64 + ck;
    float rx = px - (float)ci;
    float ry = py - (float)cj;
    float rz = pz - (float)ck;
    float rr = fmaf(rx, rx, fmaf(ry, ry, rz * rz));
    asm volatile("red.global.add.v4.f32 [%0], {%1, %2, %3, %4};"
                 :: "l"(&g_momA[c]), "f"(rx), "f"(ry), "f"(rz), "f"(rr)
                 : "memory");
    asm volatile("red.global.add.f32 [%0], %1;"
                 :: "l"(&g_momN[c]), "f"(1.0f)
                 : "memory");
}

// ---------------- kernel 2: per-cell closed form, one thread per cell -------------
__global__ __launch_bounds__(MTPB, 8) void k_main(float* __restrict__ out)
{
    __shared__ float s_row[MTPB / 32][32 * PITCH];

    int t = blockIdx.x * blockDim.x + threadIdx.x;   // cell id, natural order
    int lane = threadIdx.x & 31;
    int warp = threadIdx.x >> 5;

    float4 M = g_momA[t];
    float  nM = g_momN[t];
    g_momA[t] = make_float4(0.f, 0.f, 0.f, 0.f);     // self-reset for graph replay
    g_momN[t] = 0.f;

    float M2x = -2.f * M.x, M2y = -2.f * M.y, M2z = -2.f * M.z;
    float n2 = 2.f * nM;

    int ci = t >> 12;
    int cj = (t >> 6) & 63;
    int ck = t & 63;

    // gather 8 corner nodes as LDG.128 (node-major repacked, L2-resident)
    int base = (ci * NN + cj) * NN + ck;
    const int COFF[8] = {0, 1, NN, NN + 1, NN2, NN2 + 1, NN2 + NN, NN2 + NN + 1};
    float off[3][8];
#pragma unroll
    for (int k = 0; k < 8; k++) {
        float4 v = __ldg(g_off4 + base + COFF[k]);
        off[0][k] = v.x; off[1][k] = v.y; off[2][k] = v.z;
    }

    // edges (numpy enumeration order) + per-dim corner-coordinate sums
    const int EA[12] = {0, 0, 0, 1, 1, 2, 2, 3, 4, 4, 5, 6};
    const int EB[12] = {1, 2, 4, 3, 5, 3, 6, 7, 5, 6, 7, 7};
    const int ES[12][3] = {
        {0,0,1},{0,1,0},{1,0,0},{0,1,2},{1,0,2},{0,2,1},
        {1,2,0},{1,2,2},{2,0,1},{2,1,0},{2,1,2},{2,2,1}};

    // F_e[d] = ES_e[d]/6 + (off_A + off_B)/6
    float F[12][3];
#pragma unroll
    for (int e = 0; e < 12; e++)
#pragma unroll
        for (int d = 0; d < 3; d++)
            F[e][d] = fmaf(off[d][EA[e]] + off[d][EB[e]], (1.f / 6.f),
                           (float)ES[e][d] * (1.f / 6.f));

    // beta_b = n|F_b|^2 + F_b . M2   (b = 2..11)
    float beta[12];
#pragma unroll
    for (int b = 2; b < 12; b++) {
        float ff = fmaf(F[b][0], F[b][0], fmaf(F[b][1], F[b][1], F[b][2] * F[b][2]));
        float fd = fmaf(F[b][0], M2x, fmaf(F[b][1], M2y, F[b][2] * M2z));
        beta[b] = fmaf(nM, ff, fd);
    }

    float* sw = s_row[warp] + lane * PITCH;
    int tt = 0;

#pragma unroll
    for (int a = 1; a <= 7; a++) {
        float Gx = F[0][0] + F[a][0];
        float Gy = F[0][1] + F[a][1];
        float Gz = F[0][2] + F[a][2];
        float gg = fmaf(Gx, Gx, fmaf(Gy, Gy, Gz * Gz));
        float gd = fmaf(Gx, M2x, fmaf(Gy, M2y, Gz * M2z));
        float alpha = fmaf(nM, gg, M.w + gd);
        float Hx = n2 * Gx, Hy = n2 * Gy, Hz = n2 * Gz;
#pragma unroll
        for (int b = a + 1; b < 12; b++) {
            if (a == 7 && b == 11) break;   // 48 tris total (lex-truncated)
            float ab = alpha + beta[b];
            sw[tt] = fmaf(Hx, F[b][0], fmaf(Hy, F[b][1], fmaf(Hz, F[b][2], ab)));
            tt++;
        }
    }
    __syncwarp();

    // drain: warp's 32 rows are consecutive cells -> 6KB contiguous, float4 ops
    const float* swb = s_row[warp];
    float4* out4 = (float4*)out + (size_t)(blockIdx.x * MTPB + warp * 32) * 12;
#pragma unroll
    for (int j = 0; j < 12; j++) {
        int g4 = 32 * j + lane;          // 0..383 float4s
        int row = g4 / 12;
        int k = g4 - 12 * row;
        out4[g4] = *(const float4*)(swb + row * PITCH + 4 * k);
    }
}

extern "C" void kernel_launch(void* const* d_in, const int* in_sizes, int n_in,
                              void* d_out, int out_size) {
    const float* offset = (const float*)d_in[0];
    const float* points = (const float*)d_in[1];
    float* out = (float*)d_out;

    k_bin<<<BINBLK, BINTPB>>>(points, offset);
    k_main<<<NCELL / MTPB, MTPB>>>(out);
}